// round 4
// baseline (speedup 1.0000x reference)
#include <cuda_runtime.h>
#include <math.h>
#include <stdint.h>

#define NE    16
#define NB    512
#define NI    10
#define NF    3
#define NPROJ 7
#define NEMB  32
#define NTOT  79
#define NT    256
#define WSTR  80
#define NEB   (NE*NB)        // 8192
#define NCELL (NE*NB*NI)     // 81920
#define CHUNK 8
#define TPB   320
#define CPB   640            // cells per block
#define GRID  (NCELL/CPB)    // 128

#define INV_SQRT_DEG 0.7071067811865476f

// per-(e,b) effective weights, PAIRED layout for f32x2:
// pairs [0..28): (w0e[j][i], w1e[j][i]) ; pairs [28..35): (b0e[j], b1e[j])
// floats [70..77): wn_e*INV_SQRT_DEG ; [77] bn_e ; [78] 1-decay ; [79] pad
__device__ float g_w[NEB * WSTR];

__device__ __forceinline__ float gelu_exact(float x) {
    return 0.5f * x * (1.0f + erff(x * 0.7071067811865476f));
}

// ---------- f32x2 packed helpers ----------
__device__ __forceinline__ unsigned long long pack2(float lo, float hi) {
    unsigned long long r;
    asm("mov.b64 %0, {%1, %2};" : "=l"(r) : "f"(lo), "f"(hi));
    return r;
}
__device__ __forceinline__ void unpack2(float& lo, float& hi, unsigned long long v) {
    asm("mov.b64 {%0, %1}, %2;" : "=f"(lo), "=f"(hi) : "l"(v));
}
__device__ __forceinline__ unsigned long long fma2(unsigned long long a,
                                                   unsigned long long b,
                                                   unsigned long long c) {
    unsigned long long d;
    asm("fma.rn.f32x2 %0, %1, %2, %3;" : "=l"(d) : "l"(a), "l"(b), "l"(c));
    return d;
}
__device__ __forceinline__ unsigned long long mul2(unsigned long long a,
                                                   unsigned long long b) {
    unsigned long long d;
    asm("mul.rn.f32x2 %0, %1, %2;" : "=l"(d) : "l"(a), "l"(b));
    return d;
}

// ---------- hypernetwork ----------
template<int CNT>
__device__ __forceinline__ void do_group(const float* __restrict__ sWout,
                                         const float* __restrict__ sBout,
                                         const float* __restrict__ sBase,
                                         int row0,
                                         const float* h1,
                                         float* __restrict__ res)
{
    float on2 = 0.0f, rn2 = 0.0f;
    #pragma unroll
    for (int k = 0; k < CNT; k++) {
        const int o = row0 + k;
        float a = sBout[o];
        #pragma unroll
        for (int i = 0; i < NEMB; i++) a = fmaf(sWout[o*NEMB + i], h1[i], a);
        res[k] = a;
        on2 = fmaf(a, a, on2);
        const float w = sBase[o];
        rn2 = fmaf(w, w, rn2);
    }
    const float mx = fmaxf(sqrtf(rn2) * 0.5f, 0.01f);
    const float sc = fminf(mx / (sqrtf(on2) + 1e-8f), 1.0f);
    #pragma unroll
    for (int k = 0; k < CNT; k++)
        res[k] = sBase[row0 + k] + res[k] * sc;
}

// grid 256, block 32: e = blk>>4, b = (blk&15)*32 + tid
__global__ void hyper_kernel(
    const float* __restrict__ emb,
    const float* __restrict__ w0, const float* __restrict__ w1,
    const float* __restrict__ b0, const float* __restrict__ b1,
    const float* __restrict__ wn, const float* __restrict__ bn,
    const float* __restrict__ damping,
    const float* __restrict__ hW_in, const float* __restrict__ hb_in,
    const float* __restrict__ hW_out, const float* __restrict__ hb_out)
{
    __shared__ float sWin[NEMB*NEMB];
    __shared__ float sBin[NEMB];
    __shared__ float sWout[NTOT*NEMB];
    __shared__ float sBout[NTOT];
    __shared__ float sBase[78];
    __shared__ float sOmd;

    const int e = blockIdx.x >> 4;
    const int b = ((blockIdx.x & 15) << 5) + threadIdx.x;

    for (int i = threadIdx.x; i < NEMB*NEMB; i += 32) sWin[i]  = hW_in[e*NEMB*NEMB + i];
    for (int i = threadIdx.x; i < NTOT*NEMB; i += 32) sWout[i] = hW_out[e*NTOT*NEMB + i];
    for (int i = threadIdx.x; i < NEMB; i += 32)      sBin[i]  = hb_in[e*NEMB + i];
    for (int i = threadIdx.x; i < NTOT; i += 32)      sBout[i] = hb_out[e*NTOT + i];
    for (int i = threadIdx.x; i < 28; i += 32) {
        sBase[i]      = w0[e*28 + i];
        sBase[28 + i] = w1[e*28 + i];
    }
    for (int i = threadIdx.x; i < NPROJ; i += 32) {
        sBase[56 + i] = b0[e*NPROJ + i];
        sBase[63 + i] = b1[e*NPROJ + i];
        sBase[70 + i] = wn[e*NPROJ + i];
    }
    if (threadIdx.x == 0) {
        sBase[77] = bn[e];
        sOmd = 1.0f - 1.0f / (1.0f + expf(-damping[e]));
    }
    __syncthreads();

    float er[NEMB];
    const float* ep = emb + (e*NB + b) * NEMB;
    #pragma unroll
    for (int i = 0; i < NEMB; i++) er[i] = ep[i];

    float h1[NEMB];
    #pragma unroll
    for (int o = 0; o < NEMB; o++) {
        float a = sBin[o];
        #pragma unroll
        for (int i = 0; i < NEMB; i++) a = fmaf(sWin[o*NEMB + i], er[i], a);
        h1[o] = gelu_exact(a);
    }

    float g0[28], g1[28], g2[7], g3[7], g4[7], g5[1];
    do_group<28>(sWout, sBout, sBase, 0,  h1, g0);
    do_group<28>(sWout, sBout, sBase, 28, h1, g1);
    do_group<7 >(sWout, sBout, sBase, 56, h1, g2);
    do_group<7 >(sWout, sBout, sBase, 63, h1, g3);
    do_group<7 >(sWout, sBout, sBase, 70, h1, g4);
    do_group<1 >(sWout, sBout, sBase, 77, h1, g5);

    float* outp = g_w + (e*NB + b) * WSTR;
    #pragma unroll
    for (int k = 0; k < 28; k++) {
        outp[2*k]     = g0[k];
        outp[2*k + 1] = g1[k];
    }
    #pragma unroll
    for (int j = 0; j < NPROJ; j++) {
        outp[56 + 2*j]     = g2[j];
        outp[56 + 2*j + 1] = g3[j];
        outp[70 + j]       = g4[j] * INV_SQRT_DEG;
    }
    outp[77] = g5[0];
    outp[78] = sOmd;
    outp[79] = 0.0f;
}

// ---------- cp.async helpers ----------
__device__ __forceinline__ void cp_async16(uint32_t saddr, const void* gaddr) {
    asm volatile("cp.async.cg.shared.global [%0], [%1], 16;\n"
                 :: "r"(saddr), "l"(gaddr));
}
__device__ __forceinline__ void cp_commit() {
    asm volatile("cp.async.commit_group;\n" ::: "memory");
}
template<int N>
__device__ __forceinline__ void cp_wait() {
    asm volatile("cp.async.wait_group %0;\n" :: "n"(N) : "memory");
}

// ---------- recurrent scan ----------
// 2 cells per thread, both in the same (e,b) -> shared weight registers.
// grid=128, block=320. base cell = blk*640 (multiple of 10).
// thread t: ebl=t/5, i=t%5, cellA = base + ebl*10 + i, cellB = cellA + 5.
__global__ void __launch_bounds__(TPB, 1) rnn_kernel(
    const float* __restrict__ x,
    const float* __restrict__ h0,
    float* __restrict__ out)
{
    extern __shared__ float sx[];   // 2 * CHUNK * 640 * 3 floats = 122880 B

    const int tid  = threadIdx.x;
    const int ebl  = tid / 5;
    const int ii   = tid - ebl * 5;
    const int base = blockIdx.x * CPB;
    const int cA   = base + ebl * 10 + ii;
    const int cB   = cA + 5;
    const int eb   = blockIdx.x * (CPB/NI) + ebl;

    // ---- shared weights in registers ----
    unsigned long long wab[28];    // (w0,w1) pairs
    unsigned long long bb[NPROJ];  // (b0,b1) pairs
    unsigned long long wn2[NPROJ]; // (wn,wn)
    {
        const unsigned long long* p =
            reinterpret_cast<const unsigned long long*>(g_w + (size_t)eb * WSTR);
        #pragma unroll
        for (int k = 0; k < 28; k++) wab[k] = p[k];
        #pragma unroll
        for (int k = 0; k < NPROJ; k++) bb[k] = p[28 + k];
    }
    const float* wrow = g_w + (size_t)eb * WSTR;
    #pragma unroll
    for (int j = 0; j < NPROJ; j++) {
        const float v = wrow[70 + j];
        wn2[j] = pack2(v, v);
    }
    const float bnv = wrow[77];
    const float omdv = wrow[78];
    const unsigned long long bn2  = pack2(bnv, bnv);
    const unsigned long long omd2 = pack2(omdv, omdv);

    unsigned long long h2 = pack2(h0[cA], h0[cB]);   // (hA, hB)

    const uint32_t sbase = (uint32_t)__cvta_generic_to_shared(&sx[0]);
    const int SEGW = CPB * NF;          // 1920 words per timestep segment
    const int BUFW = CHUNK * SEGW;      // 15360 words per buffer
    const int xoffA = (ebl * 10 + ii) * NF;
    const int xoffB = xoffA + 5 * NF;

    const float* gx = x + (size_t)base * NF;    // block's float base at t=0
    float* opA = out + cA;
    float* opB = out + cB;

    // per chunk: CHUNK segs * 480 x16B = 3840 chunks; 320 threads -> 12 each
    auto fill_chunk = [&](int c, int buf) {
        const uint32_t dbase = sbase + (uint32_t)buf * (BUFW * 4);
        #pragma unroll
        for (int k = 0; k < 12; k++) {
            const int q   = tid + k * TPB;      // 0..3839
            const int tt  = q / 480;
            const int rem = q - tt * 480;
            const float* src = gx + (size_t)(c * CHUNK + tt) * ((size_t)NCELL * NF)
                                  + rem * 4;
            cp_async16(dbase + (uint32_t)(tt * (SEGW*4) + rem * 16), src);
        }
        cp_commit();
    };

    fill_chunk(0, 0);

    const int NCHUNK = NT / CHUNK;   // 32
    for (int c = 0; c < NCHUNK; c++) {
        const int buf = c & 1;
        if (c + 1 < NCHUNK) {
            fill_chunk(c + 1, buf ^ 1);
            cp_wait<1>();
        } else {
            cp_wait<0>();
        }
        __syncthreads();

        const float* sb = sx + buf * BUFW;
        #pragma unroll
        for (int tt = 0; tt < CHUNK; tt++) {
            const float xA0 = sb[tt*SEGW + xoffA];
            const float xA1 = sb[tt*SEGW + xoffA + 1];
            const float xA2 = sb[tt*SEGW + xoffA + 2];
            const float xB0 = sb[tt*SEGW + xoffB];
            const float xB1 = sb[tt*SEGW + xoffB + 1];
            const float xB2 = sb[tt*SEGW + xoffB + 2];

            float hA, hB;
            unpack2(hA, hB, h2);
            const unsigned long long xxA0 = pack2(xA0, xA0);
            const unsigned long long xxA1 = pack2(xA1, xA1);
            const unsigned long long xxA2 = pack2(xA2, xA2);
            const unsigned long long xxB0 = pack2(xB0, xB0);
            const unsigned long long xxB1 = pack2(xB1, xB1);
            const unsigned long long xxB2 = pack2(xB2, xB2);
            const unsigned long long hhA  = pack2(hA, hA);
            const unsigned long long hhB  = pack2(hB, hB);

            unsigned long long dd = bn2;    // (dA, dB)
            #pragma unroll
            for (int j = 0; j < NPROJ; j++) {
                unsigned long long accA = bb[j];
                accA = fma2(wab[4*j + 0], xxA0, accA);
                accA = fma2(wab[4*j + 1], xxA1, accA);
                accA = fma2(wab[4*j + 2], xxA2, accA);
                accA = fma2(wab[4*j + 3], hhA,  accA);
                unsigned long long accB = bb[j];
                accB = fma2(wab[4*j + 0], xxB0, accB);
                accB = fma2(wab[4*j + 1], xxB1, accB);
                accB = fma2(wab[4*j + 2], xxB2, accB);
                accB = fma2(wab[4*j + 3], hhB,  accB);
                float aA, cAv, aB, cBv;
                unpack2(aA, cAv, accA);
                unpack2(aB, cBv, accB);
                const unsigned long long aa = pack2(aA, aB);
                const unsigned long long cc = pack2(cAv, cBv);
                dd = fma2(wn2[j], mul2(aa, cc), dd);
            }
            h2 = fma2(h2, omd2, dd);

            float oA, oB;
            unpack2(oA, oB, h2);
            *opA = oA;
            *opB = oB;
            opA += NCELL;
            opB += NCELL;
        }
        __syncthreads();
    }
}

extern "C" void kernel_launch(void* const* d_in, const int* in_sizes, int n_in,
                              void* d_out, int out_size)
{
    const float* inputs    = (const float*)d_in[0];
    const float* h0        = (const float*)d_in[1];
    const float* embedding = (const float*)d_in[2];
    const float* w0        = (const float*)d_in[3];
    const float* w1        = (const float*)d_in[4];
    const float* b0        = (const float*)d_in[5];
    const float* b1        = (const float*)d_in[6];
    const float* wn        = (const float*)d_in[7];
    const float* bn        = (const float*)d_in[8];
    const float* damping   = (const float*)d_in[9];
    const float* hW_in     = (const float*)d_in[10];
    const float* hb_in     = (const float*)d_in[11];
    const float* hW_out    = (const float*)d_in[12];
    const float* hb_out    = (const float*)d_in[13];
    float* out = (float*)d_out;

    const int smem_bytes = 2 * CHUNK * CPB * NF * 4;   // 122880
    cudaFuncSetAttribute(rnn_kernel,
                         cudaFuncAttributeMaxDynamicSharedMemorySize, smem_bytes);

    hyper_kernel<<<256, 32>>>(embedding, w0, w1, b0, b1, wn, bn, damping,
                              hW_in, hb_in, hW_out, hb_out);
    rnn_kernel<<<GRID, TPB, smem_bytes>>>(inputs, h0, out);
}

// round 5
// speedup vs baseline: 1.4965x; 1.4965x over previous
#include <cuda_runtime.h>
#include <math.h>
#include <stdint.h>

#define NE    16
#define NB    512
#define NI    10
#define NF    3
#define NPROJ 7
#define NEMB  32
#define NTOT  79
#define NT    256
#define WSTR  16
#define NEB   (NE*NB)        // 8192
#define NCELL (NE*NB*NI)     // 81920
#define CHUNK 8
#define TPB   256

#define INV_SQRT_DEG 0.7071067811865476f

// Per-(e,b) quadratic-form coefficients (16 floats):
// [0]=c  [1..4)=v0,v1,v2  [4]=u_const(=v3+omd)
// [5]=A00 [6]=A11 [7]=A22 [8]=A01 [9]=A02 [10]=A12
// [11]=B0 [12]=B1 [13]=B2 [14]=S33 [15]=pad
__device__ float g_w[NEB * WSTR];

__device__ __forceinline__ float gelu_exact(float x) {
    return 0.5f * x * (1.0f + erff(x * 0.7071067811865476f));
}

// ---------- hypernetwork ----------
template<int CNT>
__device__ __forceinline__ void do_group(const float* __restrict__ sWout,
                                         const float* __restrict__ sBout,
                                         const float* __restrict__ sBase,
                                         int row0,
                                         const float* h1,
                                         float* __restrict__ res)
{
    float on2 = 0.0f, rn2 = 0.0f;
    #pragma unroll
    for (int k = 0; k < CNT; k++) {
        const int o = row0 + k;
        float a = sBout[o];
        #pragma unroll
        for (int i = 0; i < NEMB; i++) a = fmaf(sWout[o*NEMB + i], h1[i], a);
        res[k] = a;
        on2 = fmaf(a, a, on2);
        const float w = sBase[o];
        rn2 = fmaf(w, w, rn2);
    }
    const float mx = fmaxf(sqrtf(rn2) * 0.5f, 0.01f);
    const float sc = fminf(mx / (sqrtf(on2) + 1e-8f), 1.0f);
    #pragma unroll
    for (int k = 0; k < CNT; k++)
        res[k] = sBase[row0 + k] + res[k] * sc;
}

// grid 256, block 32: e = blk>>4, b = (blk&15)*32 + tid
__global__ void hyper_kernel(
    const float* __restrict__ emb,
    const float* __restrict__ w0, const float* __restrict__ w1,
    const float* __restrict__ b0, const float* __restrict__ b1,
    const float* __restrict__ wn, const float* __restrict__ bn,
    const float* __restrict__ damping,
    const float* __restrict__ hW_in, const float* __restrict__ hb_in,
    const float* __restrict__ hW_out, const float* __restrict__ hb_out)
{
    __shared__ float sWin[NEMB*NEMB];
    __shared__ float sBin[NEMB];
    __shared__ float sWout[NTOT*NEMB];
    __shared__ float sBout[NTOT];
    __shared__ float sBase[78];
    __shared__ float sOmd;

    const int e = blockIdx.x >> 4;
    const int b = ((blockIdx.x & 15) << 5) + threadIdx.x;

    for (int i = threadIdx.x; i < NEMB*NEMB; i += 32) sWin[i]  = hW_in[e*NEMB*NEMB + i];
    for (int i = threadIdx.x; i < NTOT*NEMB; i += 32) sWout[i] = hW_out[e*NTOT*NEMB + i];
    for (int i = threadIdx.x; i < NEMB; i += 32)      sBin[i]  = hb_in[e*NEMB + i];
    for (int i = threadIdx.x; i < NTOT; i += 32)      sBout[i] = hb_out[e*NTOT + i];
    for (int i = threadIdx.x; i < 28; i += 32) {
        sBase[i]      = w0[e*28 + i];
        sBase[28 + i] = w1[e*28 + i];
    }
    for (int i = threadIdx.x; i < NPROJ; i += 32) {
        sBase[56 + i] = b0[e*NPROJ + i];
        sBase[63 + i] = b1[e*NPROJ + i];
        sBase[70 + i] = wn[e*NPROJ + i];
    }
    if (threadIdx.x == 0) {
        sBase[77] = bn[e];
        sOmd = 1.0f - 1.0f / (1.0f + expf(-damping[e]));
    }
    __syncthreads();

    float er[NEMB];
    const float* ep = emb + (e*NB + b) * NEMB;
    #pragma unroll
    for (int i = 0; i < NEMB; i++) er[i] = ep[i];

    float h1[NEMB];
    #pragma unroll
    for (int o = 0; o < NEMB; o++) {
        float a = sBin[o];
        #pragma unroll
        for (int i = 0; i < NEMB; i++) a = fmaf(sWin[o*NEMB + i], er[i], a);
        h1[o] = gelu_exact(a);
    }

    float g0[28], g1[28], g2[7], g3[7], g4[7], g5[1];
    do_group<28>(sWout, sBout, sBase, 0,  h1, g0);   // w0e
    do_group<28>(sWout, sBout, sBase, 28, h1, g1);   // w1e
    do_group<7 >(sWout, sBout, sBase, 56, h1, g2);   // b0e
    do_group<7 >(sWout, sBout, sBase, 63, h1, g3);   // b1e
    do_group<7 >(sWout, sBout, sBase, 70, h1, g4);   // wn_e
    do_group<1 >(sWout, sBout, sBase, 77, h1, g5);   // bn_e

    // ---- fold into quadratic form over z = (x0,x1,x2,h) ----
    float Q[16];
    #pragma unroll
    for (int i = 0; i < 16; i++) Q[i] = 0.0f;
    float v[4] = {0.0f, 0.0f, 0.0f, 0.0f};
    float cst = g5[0];

    #pragma unroll
    for (int p = 0; p < NPROJ; p++) {
        const float wnp = g4[p] * INV_SQRT_DEG;
        #pragma unroll
        for (int i = 0; i < 4; i++) {
            const float t = wnp * g0[4*p + i];
            #pragma unroll
            for (int k = 0; k < 4; k++)
                Q[i*4 + k] = fmaf(t, g1[4*p + k], Q[i*4 + k]);
            v[i] = fmaf(wnp * g2[p], g1[4*p + i],
                   fmaf(wnp * g3[p], g0[4*p + i], v[i]));
        }
        cst = fmaf(wnp * g2[p], g3[p], cst);
    }

    float* o = g_w + (e*NB + b) * WSTR;
    o[0]  = cst;
    o[1]  = v[0];
    o[2]  = v[1];
    o[3]  = v[2];
    o[4]  = v[3] + sOmd;          // u_const
    o[5]  = Q[0];                 // A00
    o[6]  = Q[5];                 // A11
    o[7]  = Q[10];                // A22
    o[8]  = Q[1] + Q[4];          // A01
    o[9]  = Q[2] + Q[8];          // A02
    o[10] = Q[6] + Q[9];          // A12
    o[11] = Q[3] + Q[12];         // B0
    o[12] = Q[7] + Q[13];         // B1
    o[13] = Q[11] + Q[14];        // B2
    o[14] = Q[15];                // S33
    o[15] = 0.0f;
}

// ---------- cp.async helpers ----------
__device__ __forceinline__ void cp_async16(uint32_t saddr, const void* gaddr) {
    asm volatile("cp.async.cg.shared.global [%0], [%1], 16;\n"
                 :: "r"(saddr), "l"(gaddr));
}
__device__ __forceinline__ void cp_commit() {
    asm volatile("cp.async.commit_group;\n" ::: "memory");
}
template<int N>
__device__ __forceinline__ void cp_wait() {
    asm volatile("cp.async.wait_group %0;\n" :: "n"(N) : "memory");
}

// ---------- recurrent scan ----------
// One thread per cell; quadratic-form step (14 fma). x staged via cp.async.
__global__ void __launch_bounds__(TPB, 3) rnn_kernel(
    const float* __restrict__ x,
    const float* __restrict__ h0,
    float* __restrict__ out)
{
    __shared__ float sx[2][CHUNK * TPB * NF];   // 49152 B

    const int tid  = threadIdx.x;
    const int cell = blockIdx.x * TPB + tid;
    const int eb   = cell / NI;

    // ---- 16 coeffs in registers ----
    float w[WSTR];
    const float4* wp = reinterpret_cast<const float4*>(g_w + (size_t)eb * WSTR);
    #pragma unroll
    for (int q = 0; q < WSTR/4; q++) {
        float4 vv = wp[q];
        w[4*q] = vv.x; w[4*q+1] = vv.y; w[4*q+2] = vv.z; w[4*q+3] = vv.w;
    }
    const float Cc   = w[0];
    const float V0   = w[1],  V1  = w[2],  V2  = w[3];
    const float Uc   = w[4];
    const float A00  = w[5],  A11 = w[6],  A22 = w[7];
    const float A01  = w[8],  A02 = w[9],  A12 = w[10];
    const float B0   = w[11], B1  = w[12], B2  = w[13];
    const float S33  = w[14];

    float h = h0[cell];

    const float* gx = x + (size_t)blockIdx.x * TPB * NF;
    float* op = out + cell;

    const uint32_t sbase = (uint32_t)__cvta_generic_to_shared(&sx[0][0]);
    const int xoff = 3 * tid;

    // per chunk: 8 segments * 192 x16B = 1536; 256 threads -> 6 each
    auto fill_chunk = [&](int c, int buf) {
        const uint32_t dbase = sbase + (uint32_t)buf * (CHUNK * TPB * NF * 4);
        #pragma unroll
        for (int k = 0; k < 6; k++) {
            const int q   = tid + k * TPB;        // 0..1535
            const int tt  = q / 192;
            const int rem = q - tt * 192;
            const float* src = gx + (size_t)(c * CHUNK + tt) * ((size_t)NCELL * NF)
                                  + rem * 4;
            cp_async16(dbase + (uint32_t)(tt * 3072 + rem * 16), src);
        }
        cp_commit();
    };

    fill_chunk(0, 0);

    const int NCHUNK = NT / CHUNK;   // 32
    for (int c = 0; c < NCHUNK; c++) {
        const int buf = c & 1;
        if (c + 1 < NCHUNK) {
            fill_chunk(c + 1, buf ^ 1);
            cp_wait<1>();
        } else {
            cp_wait<0>();
        }
        __syncthreads();

        const float* sb = &sx[buf][0];
        #pragma unroll
        for (int tt = 0; tt < CHUNK; tt++) {
            const float x0 = sb[tt * (TPB*NF) + xoff];
            const float x1 = sb[tt * (TPB*NF) + xoff + 1];
            const float x2 = sb[tt * (TPB*NF) + xoff + 2];

            // x-only quadratic + linear
            const float q0 = fmaf(A02, x2, fmaf(A01, x1, fmaf(A00, x0, V0)));
            const float q1 = fmaf(A12, x2, fmaf(A11, x1, V1));
            const float q2 = fmaf(A22, x2, V2);
            const float g  = fmaf(q2, x2, fmaf(q1, x1, fmaf(q0, x0, Cc)));
            const float u  = fmaf(B2, x2, fmaf(B1, x1, fmaf(B0, x0, Uc)));
            // serial part: h_new = g + h*(u + S33*h)
            h = fmaf(h, fmaf(S33, h, u), g);

            *op = h;
            op += NCELL;
        }
        __syncthreads();
    }
}

extern "C" void kernel_launch(void* const* d_in, const int* in_sizes, int n_in,
                              void* d_out, int out_size)
{
    const float* inputs    = (const float*)d_in[0];
    const float* h0        = (const float*)d_in[1];
    const float* embedding = (const float*)d_in[2];
    const float* w0        = (const float*)d_in[3];
    const float* w1        = (const float*)d_in[4];
    const float* b0        = (const float*)d_in[5];
    const float* b1        = (const float*)d_in[6];
    const float* wn        = (const float*)d_in[7];
    const float* bn        = (const float*)d_in[8];
    const float* damping   = (const float*)d_in[9];
    const float* hW_in     = (const float*)d_in[10];
    const float* hb_in     = (const float*)d_in[11];
    const float* hW_out    = (const float*)d_in[12];
    const float* hb_out    = (const float*)d_in[13];
    float* out = (float*)d_out;

    hyper_kernel<<<256, 32>>>(embedding, w0, w1, b0, b1, wn, bn, damping,
                              hW_in, hb_in, hW_out, hb_out);
    rnn_kernel<<<NCELL/TPB, TPB>>>(inputs, h0, out);
}

// round 6
// speedup vs baseline: 1.7037x; 1.1385x over previous
#include <cuda_runtime.h>
#include <math.h>
#include <stdint.h>

#define NE    16
#define NB    512
#define NI    10
#define NF    3
#define NPROJ 7
#define NEMB  32
#define NROWS 78            // row 78 of the 79 hypernet outputs is unused
#define NT    256
#define WSTR  16
#define NEB   (NE*NB)        // 8192
#define NCELL (NE*NB*NI)     // 81920
#define CHUNK 8
#define TPB   256

#define INV_SQRT_DEG 0.7071067811865476f

// Per-(e,b) quadratic-form coefficients (16 floats):
// [0]=c  [1..4)=v0,v1,v2  [4]=u_const(=v3+omd)
// [5]=A00 [6]=A11 [7]=A22 [8]=A01 [9]=A02 [10]=A12
// [11]=B0 [12]=B1 [13]=B2 [14]=S33 [15]=pad
__device__ float g_w[NEB * WSTR];

__device__ __forceinline__ float gelu_exact(float x) {
    return 0.5f * x * (1.0f + erff(x * 0.7071067811865476f));
}

// ---------------- hyper kernel: 4 threads per (e,b) ----------------
// grid 128 x 256 threads. block -> e = blk/8, bbase = (blk%8)*64.
// thread t: bl = t>>2 (0..63), part = t&3. b = bbase + bl.
__global__ void __launch_bounds__(256) hyper_kernel(
    const float* __restrict__ emb,
    const float* __restrict__ w0, const float* __restrict__ w1,
    const float* __restrict__ b0, const float* __restrict__ b1,
    const float* __restrict__ wn, const float* __restrict__ bn,
    const float* __restrict__ damping,
    const float* __restrict__ hW_in, const float* __restrict__ hb_in,
    const float* __restrict__ hW_out, const float* __restrict__ hb_out)
{
    __shared__ float sWin[NEMB * 33];       // padded stride 33
    __shared__ float sBin[NEMB];
    __shared__ float sWout[79 * 33];        // padded stride 33
    __shared__ float sBout[80];
    __shared__ float sBase[78];
    __shared__ float sEff[64 * 81];         // per-b effective rows, stride 81

    const int t  = threadIdx.x;
    const int e  = blockIdx.x >> 3;
    const int bl = t >> 2;
    const int part = t & 3;
    const int b  = ((blockIdx.x & 7) << 6) + bl;

    // ---- stage per-e weights into smem (coalesced reads) ----
    for (int idx = t; idx < NEMB*NEMB; idx += 256) {
        sWin[(idx >> 5) * 33 + (idx & 31)] = hW_in[e*NEMB*NEMB + idx];
    }
    for (int idx = t; idx < 79*NEMB; idx += 256) {
        sWout[(idx >> 5) * 33 + (idx & 31)] = hW_out[e*79*NEMB + idx];
    }
    if (t < NEMB) sBin[t] = hb_in[e*NEMB + t];
    if (t < 79)   sBout[t] = hb_out[e*79 + t];
    if (t < 28) {
        sBase[t]      = w0[e*28 + t];
        sBase[28 + t] = w1[e*28 + t];
    }
    if (t < NPROJ) {
        sBase[56 + t] = b0[e*NPROJ + t];
        sBase[63 + t] = b1[e*NPROJ + t];
        sBase[70 + t] = wn[e*NPROJ + t];
    }
    if (t == 0) sBase[77] = bn[e];
    __syncthreads();

    // ---- embedding into registers ----
    float er[NEMB];
    const float* ep = emb + ((size_t)e*NB + b) * NEMB;
    #pragma unroll
    for (int i = 0; i < NEMB; i++) er[i] = ep[i];

    // ---- h1 (computed redundantly by all 4 parts) ----
    float h1[NEMB];
    #pragma unroll
    for (int o = 0; o < NEMB; o++) {
        float a = sBin[o];
        #pragma unroll
        for (int i = 0; i < NEMB; i++) a = fmaf(sWin[o*33 + i], er[i], a);
        h1[o] = gelu_exact(a);
    }

    // ---- this part's rows: o = part + 4k, o < 78 ----
    float r[20];
    float n0 = 0.f, n1 = 0.f, n2 = 0.f, n3 = 0.f, n4 = 0.f, n5 = 0.f;
    #pragma unroll
    for (int k = 0; k < 20; k++) {
        const int o = part + 4*k;
        if (o < NROWS) {
            float a = sBout[o];
            #pragma unroll
            for (int i = 0; i < NEMB; i++) a = fmaf(sWout[o*33 + i], h1[i], a);
            r[k] = a;
            const float a2 = a * a;
            if      (o < 28) n0 += a2;
            else if (o < 56) n1 += a2;
            else if (o < 63) n2 += a2;
            else if (o < 70) n3 += a2;
            else if (o < 77) n4 += a2;
            else             n5 += a2;
        } else r[k] = 0.0f;
    }

    // ---- reduce offset norms across the 4 parts (adjacent lanes) ----
    n0 += __shfl_xor_sync(0xFFFFFFFFu, n0, 1); n0 += __shfl_xor_sync(0xFFFFFFFFu, n0, 2);
    n1 += __shfl_xor_sync(0xFFFFFFFFu, n1, 1); n1 += __shfl_xor_sync(0xFFFFFFFFu, n1, 2);
    n2 += __shfl_xor_sync(0xFFFFFFFFu, n2, 1); n2 += __shfl_xor_sync(0xFFFFFFFFu, n2, 2);
    n3 += __shfl_xor_sync(0xFFFFFFFFu, n3, 1); n3 += __shfl_xor_sync(0xFFFFFFFFu, n3, 2);
    n4 += __shfl_xor_sync(0xFFFFFFFFu, n4, 1); n4 += __shfl_xor_sync(0xFFFFFFFFu, n4, 2);
    n5 += __shfl_xor_sync(0xFFFFFFFFu, n5, 1); n5 += __shfl_xor_sync(0xFFFFFFFFu, n5, 2);

    // ---- ref norms (per e, tiny) ----
    float rn0 = 0.f, rn1 = 0.f, rn2 = 0.f, rn3 = 0.f, rn4 = 0.f;
    #pragma unroll
    for (int i = 0; i < 28; i++) { rn0 = fmaf(sBase[i], sBase[i], rn0);
                                   rn1 = fmaf(sBase[28+i], sBase[28+i], rn1); }
    #pragma unroll
    for (int i = 0; i < NPROJ; i++) { rn2 = fmaf(sBase[56+i], sBase[56+i], rn2);
                                      rn3 = fmaf(sBase[63+i], sBase[63+i], rn3);
                                      rn4 = fmaf(sBase[70+i], sBase[70+i], rn4); }
    const float rn5 = sBase[77] * sBase[77];

    auto scale_of = [](float rn, float on) {
        const float mx = fmaxf(sqrtf(rn) * 0.5f, 0.01f);
        return fminf(mx / (sqrtf(on) + 1e-8f), 1.0f);
    };
    const float s0 = scale_of(rn0, n0), s1 = scale_of(rn1, n1);
    const float s2 = scale_of(rn2, n2), s3 = scale_of(rn3, n3);
    const float s4 = scale_of(rn4, n4), s5 = scale_of(rn5, n5);

    // ---- write effective rows to smem ----
    float* sE = sEff + bl * 81;
    #pragma unroll
    for (int k = 0; k < 20; k++) {
        const int o = part + 4*k;
        if (o < NROWS) {
            float sc;
            if      (o < 28) sc = s0;
            else if (o < 56) sc = s1;
            else if (o < 63) sc = s2;
            else if (o < 70) sc = s3;
            else if (o < 77) sc = s4;
            else             sc = s5;
            sE[o] = sBase[o] + r[k] * sc;
        }
    }
    __syncwarp();

    // ---- part 0: fold into quadratic form and emit 16 coeffs ----
    if (part == 0) {
        float Q[16];
        #pragma unroll
        for (int i = 0; i < 16; i++) Q[i] = 0.0f;
        float v[4] = {0.f, 0.f, 0.f, 0.f};
        float cst = sE[77];

        #pragma unroll
        for (int p = 0; p < NPROJ; p++) {
            const float wnp = sE[70 + p] * INV_SQRT_DEG;
            const float g2 = sE[56 + p], g3 = sE[63 + p];
            #pragma unroll
            for (int i = 0; i < 4; i++) {
                const float g0i = sE[4*p + i];
                const float g1i = sE[28 + 4*p + i];
                const float tq = wnp * g0i;
                #pragma unroll
                for (int k = 0; k < 4; k++)
                    Q[i*4 + k] = fmaf(tq, sE[28 + 4*p + k], Q[i*4 + k]);
                v[i] = fmaf(wnp * g2, g1i, fmaf(wnp * g3, g0i, v[i]));
            }
            cst = fmaf(wnp * g2, g3, cst);
        }

        const float omd = 1.0f - 1.0f / (1.0f + expf(-damping[e]));

        float* o = g_w + ((size_t)e*NB + b) * WSTR;
        o[0]  = cst;
        o[1]  = v[0];
        o[2]  = v[1];
        o[3]  = v[2];
        o[4]  = v[3] + omd;
        o[5]  = Q[0];
        o[6]  = Q[5];
        o[7]  = Q[10];
        o[8]  = Q[1] + Q[4];
        o[9]  = Q[2] + Q[8];
        o[10] = Q[6] + Q[9];
        o[11] = Q[3] + Q[12];
        o[12] = Q[7] + Q[13];
        o[13] = Q[11] + Q[14];
        o[14] = Q[15];
        o[15] = 0.0f;
    }
}

// ---------- cp.async helpers ----------
__device__ __forceinline__ void cp_async16(uint32_t saddr, const void* gaddr) {
    asm volatile("cp.async.cg.shared.global [%0], [%1], 16;\n"
                 :: "r"(saddr), "l"(gaddr));
}
__device__ __forceinline__ void cp_commit() {
    asm volatile("cp.async.commit_group;\n" ::: "memory");
}
template<int N>
__device__ __forceinline__ void cp_wait() {
    asm volatile("cp.async.wait_group %0;\n" :: "n"(N) : "memory");
}

// ---------- recurrent scan (unchanged from R5 winner) ----------
__global__ void __launch_bounds__(TPB, 3) rnn_kernel(
    const float* __restrict__ x,
    const float* __restrict__ h0,
    float* __restrict__ out)
{
    __shared__ float sx[2][CHUNK * TPB * NF];   // 49152 B

    const int tid  = threadIdx.x;
    const int cell = blockIdx.x * TPB + tid;
    const int eb   = cell / NI;

    float w[WSTR];
    const float4* wp = reinterpret_cast<const float4*>(g_w + (size_t)eb * WSTR);
    #pragma unroll
    for (int q = 0; q < WSTR/4; q++) {
        float4 vv = wp[q];
        w[4*q] = vv.x; w[4*q+1] = vv.y; w[4*q+2] = vv.z; w[4*q+3] = vv.w;
    }
    const float Cc   = w[0];
    const float V0   = w[1],  V1  = w[2],  V2  = w[3];
    const float Uc   = w[4];
    const float A00  = w[5],  A11 = w[6],  A22 = w[7];
    const float A01  = w[8],  A02 = w[9],  A12 = w[10];
    const float B0   = w[11], B1  = w[12], B2  = w[13];
    const float S33  = w[14];

    float h = h0[cell];

    const float* gx = x + (size_t)blockIdx.x * TPB * NF;
    float* op = out + cell;

    const uint32_t sbase = (uint32_t)__cvta_generic_to_shared(&sx[0][0]);
    const int xoff = 3 * tid;

    auto fill_chunk = [&](int c, int buf) {
        const uint32_t dbase = sbase + (uint32_t)buf * (CHUNK * TPB * NF * 4);
        #pragma unroll
        for (int k = 0; k < 6; k++) {
            const int q   = tid + k * TPB;        // 0..1535
            const int tt  = q / 192;
            const int rem = q - tt * 192;
            const float* src = gx + (size_t)(c * CHUNK + tt) * ((size_t)NCELL * NF)
                                  + rem * 4;
            cp_async16(dbase + (uint32_t)(tt * 3072 + rem * 16), src);
        }
        cp_commit();
    };

    fill_chunk(0, 0);

    const int NCHUNK = NT / CHUNK;   // 32
    for (int c = 0; c < NCHUNK; c++) {
        const int buf = c & 1;
        if (c + 1 < NCHUNK) {
            fill_chunk(c + 1, buf ^ 1);
            cp_wait<1>();
        } else {
            cp_wait<0>();
        }
        __syncthreads();

        const float* sb = &sx[buf][0];
        #pragma unroll
        for (int tt = 0; tt < CHUNK; tt++) {
            const float x0 = sb[tt * (TPB*NF) + xoff];
            const float x1 = sb[tt * (TPB*NF) + xoff + 1];
            const float x2 = sb[tt * (TPB*NF) + xoff + 2];

            const float q0 = fmaf(A02, x2, fmaf(A01, x1, fmaf(A00, x0, V0)));
            const float q1 = fmaf(A12, x2, fmaf(A11, x1, V1));
            const float q2 = fmaf(A22, x2, V2);
            const float g  = fmaf(q2, x2, fmaf(q1, x1, fmaf(q0, x0, Cc)));
            const float u  = fmaf(B2, x2, fmaf(B1, x1, fmaf(B0, x0, Uc)));
            h = fmaf(h, fmaf(S33, h, u), g);

            *op = h;
            op += NCELL;
        }
        __syncthreads();
    }
}

extern "C" void kernel_launch(void* const* d_in, const int* in_sizes, int n_in,
                              void* d_out, int out_size)
{
    const float* inputs    = (const float*)d_in[0];
    const float* h0        = (const float*)d_in[1];
    const float* embedding = (const float*)d_in[2];
    const float* w0        = (const float*)d_in[3];
    const float* w1        = (const float*)d_in[4];
    const float* b0        = (const float*)d_in[5];
    const float* b1        = (const float*)d_in[6];
    const float* wn        = (const float*)d_in[7];
    const float* bn        = (const float*)d_in[8];
    const float* damping   = (const float*)d_in[9];
    const float* hW_in     = (const float*)d_in[10];
    const float* hb_in     = (const float*)d_in[11];
    const float* hW_out    = (const float*)d_in[12];
    const float* hb_out    = (const float*)d_in[13];
    float* out = (float*)d_out;

    hyper_kernel<<<128, 256>>>(embedding, w0, w1, b0, b1, wn, bn, damping,
                               hW_in, hb_in, hW_out, hb_out);
    rnn_kernel<<<NCELL/TPB, TPB>>>(inputs, h0, out);
}

// round 7
// speedup vs baseline: 1.8312x; 1.0749x over previous
#include <cuda_runtime.h>
#include <math.h>
#include <stdint.h>

#define NE    16
#define NB    512
#define NI    10
#define NF    3
#define NPROJ 7
#define NEMB  32
#define NROWS 78
#define NT    256
#define NEB   (NE*NB)        // 8192
#define NCELL (NE*NB*NI)     // 81920
#define CHUNK 8
#define TPB   256
#define NEBL  27             // max distinct (e,b) per 256-cell block

#define INV_SQRT_DEG 0.7071067811865476f

// dynamic smem layout (floats):
// [0..432)      sCoef  27*16        (persists through scan)
// [448..12736)  sx     double buffer 2*CHUNK*TPB*NF = 12288 floats
// prologue scratch OVERLAPS sx:
//   sWin  448..1504     (32*33)
//   sWout 1504..4078    (78*33)
//   sBin  4078..4110    (32)
//   sBout 4110..4188    (78)
//   sBase 4188..4266    (78)
//   sH1   4268..5159    (27*33)
//   sEff  5160..7347    (27*81)
#define SMEM_FLOATS (448 + 2*CHUNK*TPB*NF)   // 12736 -> 50944 B

__device__ __forceinline__ float gelu_exact(float x) {
    return 0.5f * x * (1.0f + erff(x * 0.7071067811865476f));
}

__device__ __forceinline__ void cp_async16(uint32_t saddr, const void* gaddr) {
    asm volatile("cp.async.cg.shared.global [%0], [%1], 16;\n"
                 :: "r"(saddr), "l"(gaddr));
}
__device__ __forceinline__ void cp_commit() {
    asm volatile("cp.async.commit_group;\n" ::: "memory");
}
template<int N>
__device__ __forceinline__ void cp_wait() {
    asm volatile("cp.async.wait_group %0;\n" :: "n"(N) : "memory");
}

__global__ void __launch_bounds__(TPB, 3) fused_kernel(
    const float* __restrict__ x,
    const float* __restrict__ h0,
    const float* __restrict__ emb,
    const float* __restrict__ w0, const float* __restrict__ w1,
    const float* __restrict__ b0, const float* __restrict__ b1,
    const float* __restrict__ wn, const float* __restrict__ bn,
    const float* __restrict__ damping,
    const float* __restrict__ hW_in, const float* __restrict__ hb_in,
    const float* __restrict__ hW_out, const float* __restrict__ hb_out,
    float* __restrict__ out)
{
    extern __shared__ float sm[];
    float* sCoef = sm;               // 432 floats
    float* sx    = sm + 448;         // 12288 floats
    float* sWin  = sx;
    float* sWout = sx + 1056;
    float* sBin  = sx + 3630;
    float* sBout = sx + 4110 - 432;  // = sx+3678? compute explicitly below
    // use explicit offsets to avoid mistakes:
    sBin         = sx + 3630;        // 32
    float* sBo   = sx + 3662;        // 78  (hypernet output bias)
    float* sBase = sx + 3740;        // 78
    float* sH1   = sx + 3820;        // 27*33 = 891
    float* sEff  = sx + 4712;        // 27*81 = 2187  (ends 6899 < 12288)

    const int tid = threadIdx.x;
    const int blk = blockIdx.x;
    const int e   = blk / 20;                 // 20 blocks per ensemble
    const int eb0 = (blk * TPB) / NI;         // first (e,b) index of this block
    const int cell = blk * TPB + tid;

    // ================= PROLOGUE: per-block hypernetwork =================
    // stage per-e weights into smem (coalesced)
    for (int idx = tid; idx < NEMB*NEMB; idx += TPB)
        sWin[(idx >> 5) * 33 + (idx & 31)] = hW_in[e*NEMB*NEMB + idx];
    for (int idx = tid; idx < NROWS*NEMB; idx += TPB)
        sWout[(idx >> 5) * 33 + (idx & 31)] = hW_out[e*79*NEMB + idx];
    if (tid < NEMB)  sBin[tid] = hb_in[e*NEMB + tid];
    if (tid < NROWS) sBo[tid]  = hb_out[e*79 + tid];
    if (tid < 28) {
        sBase[tid]      = w0[e*28 + tid];
        sBase[28 + tid] = w1[e*28 + tid];
    }
    if (tid < NPROJ) {
        sBase[56 + tid] = b0[e*NPROJ + tid];
        sBase[63 + tid] = b1[e*NPROJ + tid];
        sBase[70 + tid] = wn[e*NPROJ + tid];
    }
    if (tid == 0) sBase[77] = bn[e];
    __syncthreads();

    if (tid < NEBL * 8) {
        const int ebl  = tid >> 3;
        const int part = tid & 7;
        const int ebg  = (eb0 + ebl < NEB) ? (eb0 + ebl) : (NEB - 1);
        const unsigned lane = tid & 31;
        const unsigned gmask = 0xFFu << (lane & ~7u);

        // embedding -> regs (redundant per part; cached)
        float er[NEMB];
        const float* ep = emb + (size_t)ebg * NEMB;
        #pragma unroll
        for (int i = 0; i < NEMB; i++) er[i] = ep[i];

        // h1 split: this part computes rows part*4 .. part*4+3
        #pragma unroll
        for (int j = 0; j < 4; j++) {
            const int o = part * 4 + j;
            float a = sBin[o];
            #pragma unroll
            for (int i = 0; i < NEMB; i++) a = fmaf(sWin[o*33 + i], er[i], a);
            sH1[ebl*33 + o] = gelu_exact(a);
        }
        __syncwarp(gmask);

        // output rows: o = part + 8k
        float r[10];
        float n0 = 0.f, n1 = 0.f, n2 = 0.f, n3 = 0.f, n4 = 0.f, n5 = 0.f;
        const float* h1p = sH1 + ebl*33;
        #pragma unroll
        for (int k = 0; k < 10; k++) {
            const int o = part + 8*k;
            if (o < NROWS) {
                float a = sBo[o];
                #pragma unroll
                for (int i = 0; i < NEMB; i++) a = fmaf(sWout[o*33 + i], h1p[i], a);
                r[k] = a;
                const float a2 = a * a;
                if      (o < 28) n0 += a2;
                else if (o < 56) n1 += a2;
                else if (o < 63) n2 += a2;
                else if (o < 70) n3 += a2;
                else if (o < 77) n4 += a2;
                else             n5 += a2;
            } else r[k] = 0.0f;
        }
        #pragma unroll
        for (int d = 1; d <= 4; d <<= 1) {
            n0 += __shfl_xor_sync(gmask, n0, d);
            n1 += __shfl_xor_sync(gmask, n1, d);
            n2 += __shfl_xor_sync(gmask, n2, d);
            n3 += __shfl_xor_sync(gmask, n3, d);
            n4 += __shfl_xor_sync(gmask, n4, d);
            n5 += __shfl_xor_sync(gmask, n5, d);
        }

        // reference norms (per e)
        float rn0 = 0.f, rn1 = 0.f, rn2 = 0.f, rn3 = 0.f, rn4 = 0.f;
        #pragma unroll
        for (int i = 0; i < 28; i++) { rn0 = fmaf(sBase[i], sBase[i], rn0);
                                       rn1 = fmaf(sBase[28+i], sBase[28+i], rn1); }
        #pragma unroll
        for (int i = 0; i < NPROJ; i++) { rn2 = fmaf(sBase[56+i], sBase[56+i], rn2);
                                          rn3 = fmaf(sBase[63+i], sBase[63+i], rn3);
                                          rn4 = fmaf(sBase[70+i], sBase[70+i], rn4); }
        const float rn5 = sBase[77] * sBase[77];

        auto scale_of = [](float rn, float on) {
            const float mx = fmaxf(sqrtf(rn) * 0.5f, 0.01f);
            return fminf(mx / (sqrtf(on) + 1e-8f), 1.0f);
        };
        const float s0 = scale_of(rn0, n0), s1 = scale_of(rn1, n1);
        const float s2 = scale_of(rn2, n2), s3 = scale_of(rn3, n3);
        const float s4 = scale_of(rn4, n4), s5 = scale_of(rn5, n5);

        float* sE = sEff + ebl * 81;
        #pragma unroll
        for (int k = 0; k < 10; k++) {
            const int o = part + 8*k;
            if (o < NROWS) {
                float sc;
                if      (o < 28) sc = s0;
                else if (o < 56) sc = s1;
                else if (o < 63) sc = s2;
                else if (o < 70) sc = s3;
                else if (o < 77) sc = s4;
                else             sc = s5;
                sE[o] = sBase[o] + r[k] * sc;
            }
        }
        __syncwarp(gmask);

        if (part == 0) {
            float Q[16];
            #pragma unroll
            for (int i = 0; i < 16; i++) Q[i] = 0.0f;
            float v[4] = {0.f, 0.f, 0.f, 0.f};
            float cst = sE[77];

            #pragma unroll
            for (int p = 0; p < NPROJ; p++) {
                const float wnp = sE[70 + p] * INV_SQRT_DEG;
                const float g2 = sE[56 + p], g3 = sE[63 + p];
                #pragma unroll
                for (int i = 0; i < 4; i++) {
                    const float g0i = sE[4*p + i];
                    const float g1i = sE[28 + 4*p + i];
                    const float tq = wnp * g0i;
                    #pragma unroll
                    for (int k = 0; k < 4; k++)
                        Q[i*4 + k] = fmaf(tq, sE[28 + 4*p + k], Q[i*4 + k]);
                    v[i] = fmaf(wnp * g2, g1i, fmaf(wnp * g3, g0i, v[i]));
                }
                cst = fmaf(wnp * g2, g3, cst);
            }

            const float omd = 1.0f - 1.0f / (1.0f + expf(-damping[e]));

            float* oc = sCoef + ebl * 16;
            oc[0]  = cst;
            oc[1]  = v[0];
            oc[2]  = v[1];
            oc[3]  = v[2];
            oc[4]  = v[3] + omd;
            oc[5]  = Q[0];
            oc[6]  = Q[5];
            oc[7]  = Q[10];
            oc[8]  = Q[1] + Q[4];
            oc[9]  = Q[2] + Q[8];
            oc[10] = Q[6] + Q[9];
            oc[11] = Q[3] + Q[12];
            oc[12] = Q[7] + Q[13];
            oc[13] = Q[11] + Q[14];
            oc[14] = Q[15];
            oc[15] = 0.0f;
        }
    }
    __syncthreads();

    // ================= per-thread coefficients =================
    const int myl = cell / NI - eb0;
    const float* oc = sCoef + myl * 16;
    const float Cc  = oc[0];
    const float V0  = oc[1],  V1  = oc[2],  V2  = oc[3];
    const float Uc  = oc[4];
    const float A00 = oc[5],  A11 = oc[6],  A22 = oc[7];
    const float A01 = oc[8],  A02 = oc[9],  A12 = oc[10];
    const float B0  = oc[11], B1  = oc[12], B2  = oc[13];
    const float S33 = oc[14];

    float h = h0[cell];
    __syncthreads();   // all sCoef reads done before... (sCoef not overwritten; safety vs sx reuse timing)

    // ================= recurrent scan (R5 structure) =================
    const float* gx = x + (size_t)blk * TPB * NF;
    float* op = out + cell;

    const uint32_t sbase = (uint32_t)__cvta_generic_to_shared(sx);
    const int xoff = 3 * tid;

    auto fill_chunk = [&](int c, int buf) {
        const uint32_t dbase = sbase + (uint32_t)buf * (CHUNK * TPB * NF * 4);
        #pragma unroll
        for (int k = 0; k < 6; k++) {
            const int q   = tid + k * TPB;        // 0..1535
            const int tt  = q / 192;
            const int rem = q - tt * 192;
            const float* src = gx + (size_t)(c * CHUNK + tt) * ((size_t)NCELL * NF)
                                  + rem * 4;
            cp_async16(dbase + (uint32_t)(tt * 3072 + rem * 16), src);
        }
        cp_commit();
    };

    fill_chunk(0, 0);

    const int NCHUNK = NT / CHUNK;   // 32
    for (int c = 0; c < NCHUNK; c++) {
        const int buf = c & 1;
        if (c + 1 < NCHUNK) {
            fill_chunk(c + 1, buf ^ 1);
            cp_wait<1>();
        } else {
            cp_wait<0>();
        }
        __syncthreads();

        const float* sb = sx + buf * (CHUNK * TPB * NF);
        #pragma unroll
        for (int tt = 0; tt < CHUNK; tt++) {
            const float x0 = sb[tt * (TPB*NF) + xoff];
            const float x1 = sb[tt * (TPB*NF) + xoff + 1];
            const float x2 = sb[tt * (TPB*NF) + xoff + 2];

            const float q0 = fmaf(A02, x2, fmaf(A01, x1, fmaf(A00, x0, V0)));
            const float q1 = fmaf(A12, x2, fmaf(A11, x1, V1));
            const float q2 = fmaf(A22, x2, V2);
            const float g  = fmaf(q2, x2, fmaf(q1, x1, fmaf(q0, x0, Cc)));
            const float u  = fmaf(B2, x2, fmaf(B1, x1, fmaf(B0, x0, Uc)));
            h = fmaf(h, fmaf(S33, h, u), g);

            *op = h;
            op += NCELL;
        }
        __syncthreads();
    }
}

extern "C" void kernel_launch(void* const* d_in, const int* in_sizes, int n_in,
                              void* d_out, int out_size)
{
    const float* inputs    = (const float*)d_in[0];
    const float* h0        = (const float*)d_in[1];
    const float* embedding = (const float*)d_in[2];
    const float* w0        = (const float*)d_in[3];
    const float* w1        = (const float*)d_in[4];
    const float* b0        = (const float*)d_in[5];
    const float* b1        = (const float*)d_in[6];
    const float* wn        = (const float*)d_in[7];
    const float* bn        = (const float*)d_in[8];
    const float* damping   = (const float*)d_in[9];
    const float* hW_in     = (const float*)d_in[10];
    const float* hb_in     = (const float*)d_in[11];
    const float* hW_out    = (const float*)d_in[12];
    const float* hb_out    = (const float*)d_in[13];
    float* out = (float*)d_out;

    const int smem_bytes = SMEM_FLOATS * 4;   // 50944
    cudaFuncSetAttribute(fused_kernel,
                         cudaFuncAttributeMaxDynamicSharedMemorySize, smem_bytes);

    fused_kernel<<<NCELL/TPB, TPB, smem_bytes>>>(
        inputs, h0, embedding, w0, w1, b0, b1, wn, bn, damping,
        hW_in, hb_in, hW_out, hb_out, out);
}